// round 15
// baseline (speedup 1.0000x reference)
#include <cuda_runtime.h>

#define B_   32
#define C_   4
#define N_   16384
#define RES_ 32
#define NVOX (B_ * RES_ * RES_ * RES_)    // 1048576
#define NB   1024                         // 32 blocks per batch, 512 pts each

// Scratch (allocation-free).
__device__ float4 g_cp_pad[NVOX];         // 16 MB padded copy of voxel_grid_cp
__device__ float  g_partials[NB];
__device__ int    g_batch_ready[B_];      // zero-init; reset by tail each run
__device__ int    g_count = 0;            // reset by tail each run

// ---------------------------------------------------------------------------
// Single fused kernel. All 1024 CTAs co-resident (regs<=32 REQUIRED: 8 CTA/SM
// x 148 SMs = 1184 slots >= 1024; fewer would deadlock the spin).
// Phase 1: pad 1/32 of my batch's cp slice (.cg reads so cp stays L2-resident
//          across graph replays — .cs was forcing a DRAM refetch every replay).
// Phase 2: precompute ALL 8 gather offsets, THEN release-publish + relaxed spin
//          (no acquire -> no L1 invalidate), so gathers issue immediately after.
// Phase 3: 8 ILP gathers via ld.global.cg.v4; r-vectors recomputed under load
//          latency; deterministic block reduction.
// Tail   : last block reduces partials + regularizer, resets counters.
// ---------------------------------------------------------------------------
__global__ void __launch_bounds__(256, 8) refl_kernel(const float* __restrict__ y_pred,
                                                      const float* __restrict__ points,
                                                      const float4* __restrict__ cp4,
                                                      float* __restrict__ out) {
    const int b  = blockIdx.x >> 5;               // batch
    const int j  = blockIdx.x & 31;               // sub-block within batch
    const int n0 = j << 9;                        // first of 512 points

    // ---- Phase 1: pad my 1024-voxel slice (4 voxels/thread)
    {
        const int v0 = (b << 15) + (j << 10);     // first voxel of slice
        const float4* src = cp4 + ((v0 * 3) >> 2) + 3 * threadIdx.x;
        float4 a, c0, c1;
        asm volatile("ld.global.cg.v4.f32 {%0,%1,%2,%3}, [%4];"
                     : "=f"(a.x), "=f"(a.y), "=f"(a.z), "=f"(a.w) : "l"(src + 0));
        asm volatile("ld.global.cg.v4.f32 {%0,%1,%2,%3}, [%4];"
                     : "=f"(c0.x), "=f"(c0.y), "=f"(c0.z), "=f"(c0.w) : "l"(src + 1));
        asm volatile("ld.global.cg.v4.f32 {%0,%1,%2,%3}, [%4];"
                     : "=f"(c1.x), "=f"(c1.y), "=f"(c1.z), "=f"(c1.w) : "l"(src + 2));
        float4* dst = g_cp_pad + v0 + (threadIdx.x << 2);
        asm volatile("st.global.cg.v4.f32 [%0], {%1,%2,%3,%4};"
                     :: "l"(dst + 0), "f"(a.x),  "f"(a.y),  "f"(a.z),  "f"(0.0f) : "memory");
        asm volatile("st.global.cg.v4.f32 [%0], {%1,%2,%3,%4};"
                     :: "l"(dst + 1), "f"(a.w),  "f"(c0.x), "f"(c0.y), "f"(0.0f) : "memory");
        asm volatile("st.global.cg.v4.f32 [%0], {%1,%2,%3,%4};"
                     :: "l"(dst + 2), "f"(c0.z), "f"(c0.w), "f"(c1.x), "f"(0.0f) : "memory");
        asm volatile("st.global.cg.v4.f32 [%0], {%1,%2,%3,%4};"
                     :: "l"(dst + 3), "f"(c1.y), "f"(c1.z), "f"(c1.w), "f"(0.0f) : "memory");
    }

    // ---- Load planes + stage this block's 512 points while pad stores drain
    __shared__ float4 plane[4];
    __shared__ float  spts[1536];                 // 512 points * xyz
    if (threadIdx.x < 4) {
        const float* yp = y_pred + (b * 4 + threadIdx.x) * 4;
        float nx = yp[0], ny = yp[1], nz = yp[2];
        float inv = rsqrtf(nx*nx + ny*ny + nz*nz);
        plane[threadIdx.x] = make_float4(nx*inv, ny*inv, nz*inv, yp[3]);
    }
    {
        const float4* src = (const float4*)(points + ((size_t)b * N_ + n0) * 3);
        ((float4*)spts)[threadIdx.x] = src[threadIdx.x];
        if (threadIdx.x < 128)
            ((float4*)spts)[threadIdx.x + 256] = src[threadIdx.x + 256];
    }
    __syncthreads();                              // spts/plane ready; pad stores issued

    // ---- Precompute ALL 8 gather offsets BEFORE waiting (loads issue at spin exit)
    int off[8];
#pragma unroll
    for (int k = 0; k < 2; k++) {
        const int p = threadIdx.x + (k << 8);
        const float px = spts[3 * p + 0];
        const float py = spts[3 * p + 1];
        const float pz = spts[3 * p + 2];
#pragma unroll
        for (int c = 0; c < 4; c++) {
            float4 pl = plane[c];
            float t  = 2.0f * (px*pl.x + py*pl.y + pz*pl.z + pl.w);
            float rx = fmaf(-t, pl.x, px);
            float ry = fmaf(-t, pl.y, py);
            float rz = fmaf(-t, pl.z, pz);
            int v0 = min(RES_ - 1, max(0, __float2int_rd(rx * (float)RES_)));
            int v1 = min(RES_ - 1, max(0, __float2int_rd(ry * (float)RES_)));
            int v2 = min(RES_ - 1, max(0, __float2int_rd(rz * (float)RES_)));
            off[k * 4 + c] = (v0 << 10) | (v1 << 5) | v2;
        }
    }

    // ---- Publish my pad slice; RELAXED spin until whole batch slice is ready
    if (threadIdx.x == 0) {
        int seen;
        asm volatile("atom.release.gpu.global.add.s32 %0, [%1], 1;"
                     : "=r"(seen) : "l"(&g_batch_ready[b]) : "memory");
        if (seen + 1 < 32) {
            int r;
            do {
                __nanosleep(32);
                asm volatile("ld.relaxed.gpu.global.s32 %0, [%1];"
                             : "=r"(r) : "l"(&g_batch_ready[b]) : "memory");
            } while (r < 32);
        }
    }
    __syncthreads();                              // batch slice fully padded

    // ---- Phase 3: gathers (L2-direct); recompute r-vectors under load latency
    const float4* cpb = g_cp_pad + (b << 15);
    float acc = 0.0f;
#pragma unroll
    for (int k = 0; k < 2; k++) {
        float4 cv[4];
#pragma unroll
        for (int c = 0; c < 4; c++) {
            const float4* gp = cpb + off[k * 4 + c];
            asm volatile("ld.global.cg.v4.f32 {%0,%1,%2,%3}, [%4];"
                         : "=f"(cv[c].x), "=f"(cv[c].y), "=f"(cv[c].z), "=f"(cv[c].w)
                         : "l"(gp));
        }
        const int p = threadIdx.x + (k << 8);
        const float px = spts[3 * p + 0];
        const float py = spts[3 * p + 1];
        const float pz = spts[3 * p + 2];
#pragma unroll
        for (int c = 0; c < 4; c++) {
            float4 pl = plane[c];
            float t  = 2.0f * (px*pl.x + py*pl.y + pz*pl.z + pl.w);
            float rx = fmaf(-t, pl.x, px);
            float ry = fmaf(-t, pl.y, py);
            float rz = fmaf(-t, pl.z, pz);
            float dx = rx - cv[c].x, dy = ry - cv[c].y, dz = rz - cv[c].z;
            acc += sqrtf(fmaf(dx, dx, fmaf(dy, dy, dz * dz)));
        }
    }

    // ---- Deterministic block reduction
#pragma unroll
    for (int o = 16; o >= 1; o >>= 1)
        acc += __shfl_xor_sync(0xffffffffu, acc, o);
    __shared__ float ws[8];
    const int wid = threadIdx.x >> 5;
    if ((threadIdx.x & 31) == 0) ws[wid] = acc;
    __syncthreads();

    __shared__ bool is_last;
    if (threadIdx.x == 0) {
        float s = 0.0f;
#pragma unroll
        for (int w = 0; w < 8; w++) s += ws[w];
        asm volatile("st.global.cg.f32 [%0], %1;"
                     :: "l"(&g_partials[blockIdx.x]), "f"(s) : "memory");
        int done;
        asm volatile("atom.release.gpu.global.add.s32 %0, [%1], 1;"
                     : "=r"(done) : "l"(&g_count) : "memory");
        is_last = (done == NB - 1);
    }
    __syncthreads();
    if (!is_last) return;

    // ---- Tail: last block only (single acquire fence total)
    asm volatile("fence.acq_rel.gpu;" ::: "memory");

    __shared__ float reg_s;
    if (threadIdx.x < 32) {
        const float* yp = y_pred + threadIdx.x * 16;
        float nh[4][3];
#pragma unroll
        for (int c = 0; c < 4; c++) {
            float nx = yp[c*4+0], ny = yp[c*4+1], nz = yp[c*4+2];
            float inv = rsqrtf(nx*nx + ny*ny + nz*nz);
            nh[c][0] = nx*inv; nh[c][1] = ny*inv; nh[c][2] = nz*inv;
        }
        float s = 0.0f;
#pragma unroll
        for (int c = 0; c < 4; c++)
#pragma unroll
            for (int e = 0; e < 4; e++) {
                float g = nh[c][0]*nh[e][0] + nh[c][1]*nh[e][1] + nh[c][2]*nh[e][2]
                          - (c == e ? 1.0f : 0.0f);
                s += g * g;
            }
        float reg = sqrtf(s);
#pragma unroll
        for (int o = 16; o >= 1; o >>= 1)
            reg += __shfl_xor_sync(0xffffffffu, reg, o);
        if (threadIdx.x == 0) reg_s = 25.0f * reg * (1.0f / (float)B_);
    }

    __shared__ float red[256];
    float a0, a1, a2, a3;
    {
        const float* p = g_partials;
        int i = threadIdx.x;
        asm volatile("ld.global.cg.f32 %0, [%1];" : "=f"(a0) : "l"(p + i));
        asm volatile("ld.global.cg.f32 %0, [%1];" : "=f"(a1) : "l"(p + i + 256));
        asm volatile("ld.global.cg.f32 %0, [%1];" : "=f"(a2) : "l"(p + i + 512));
        asm volatile("ld.global.cg.f32 %0, [%1];" : "=f"(a3) : "l"(p + i + 768));
    }
    red[threadIdx.x] = (a0 + a1) + (a2 + a3);
    __syncthreads();
#pragma unroll
    for (int stride = 128; stride >= 1; stride >>= 1) {
        if (threadIdx.x < stride) red[threadIdx.x] += red[threadIdx.x + stride];
        __syncthreads();
    }
    if (threadIdx.x == 0) {
        out[0] = red[0] * (1.0f / (float)N_) + reg_s;
        // Reset counters for the next graph replay (kernel boundary publishes).
#pragma unroll
        for (int i = 0; i < B_; i++) g_batch_ready[i] = 0;
        g_count = 0;
    }
}

extern "C" void kernel_launch(void* const* d_in, const int* in_sizes, int n_in,
                              void* d_out, int out_size) {
    const float* y_pred = (const float*)d_in[0];
    const float* points = (const float*)d_in[1];
    // d_in[2] = voxel_grid — unused by the reference math.
    const float4* cp4   = (const float4*)d_in[3];
    float* out = (float*)d_out;

    refl_kernel<<<NB, 256>>>(y_pred, points, cp4, out);
}

// round 16
// speedup vs baseline: 1.1089x; 1.1089x over previous
#include <cuda_runtime.h>

#define B_   32
#define C_   4
#define N_   16384
#define RES_ 32
#define NVOX (B_ * RES_ * RES_ * RES_)    // 1048576
#define NB   1024                         // 32 blocks per batch, 512 pts each

// Scratch (allocation-free).
__device__ float4 g_cp_pad[NVOX];         // 16 MB padded copy of voxel_grid_cp
__device__ float  g_partials[NB];
__device__ int    g_batch_ready[B_];      // zero-init; reset by tail each run
__device__ int    g_count = 0;            // reset by tail each run

// ---------------------------------------------------------------------------
// Single fused kernel. All 1024 CTAs co-resident (regs<=32 REQUIRED: 8 CTA/SM
// x 148 SMs = 1184 slots >= 1024; fewer would deadlock the spin).
// Phase 1: pad 1/32 of my batch's cp slice (.cg both ways; cp stays L2-warm).
// Phase 2: compute all 8 gather offsets + reflected coords, release-publish,
//          relaxed spin (no acquire anywhere in hot path -> no L1 invalidates).
// Phase 3: 8 gathers (2 batches of 4, off[] independent so loads pipeline),
//          two-accumulator reduction, deterministic block+grid reduce.
// ---------------------------------------------------------------------------
__global__ void __launch_bounds__(256, 8) refl_kernel(const float* __restrict__ y_pred,
                                                      const float* __restrict__ points,
                                                      const float4* __restrict__ cp4,
                                                      float* __restrict__ out) {
    const int b  = blockIdx.x >> 5;               // batch
    const int j  = blockIdx.x & 31;               // sub-block within batch
    const int n0 = j << 9;                        // first of 512 points

    // ---- Phase 1: pad my 1024-voxel slice (4 voxels/thread)
    {
        const int v0 = (b << 15) + (j << 10);
        const float4* src = cp4 + ((v0 * 3) >> 2) + 3 * threadIdx.x;
        float4 a, c0, c1;
        asm volatile("ld.global.cg.v4.f32 {%0,%1,%2,%3}, [%4];"
                     : "=f"(a.x), "=f"(a.y), "=f"(a.z), "=f"(a.w) : "l"(src + 0));
        asm volatile("ld.global.cg.v4.f32 {%0,%1,%2,%3}, [%4];"
                     : "=f"(c0.x), "=f"(c0.y), "=f"(c0.z), "=f"(c0.w) : "l"(src + 1));
        asm volatile("ld.global.cg.v4.f32 {%0,%1,%2,%3}, [%4];"
                     : "=f"(c1.x), "=f"(c1.y), "=f"(c1.z), "=f"(c1.w) : "l"(src + 2));
        float4* dst = g_cp_pad + v0 + (threadIdx.x << 2);
        asm volatile("st.global.cg.v4.f32 [%0], {%1,%2,%3,%4};"
                     :: "l"(dst + 0), "f"(a.x),  "f"(a.y),  "f"(a.z),  "f"(0.0f) : "memory");
        asm volatile("st.global.cg.v4.f32 [%0], {%1,%2,%3,%4};"
                     :: "l"(dst + 1), "f"(a.w),  "f"(c0.x), "f"(c0.y), "f"(0.0f) : "memory");
        asm volatile("st.global.cg.v4.f32 [%0], {%1,%2,%3,%4};"
                     :: "l"(dst + 2), "f"(c0.z), "f"(c0.w), "f"(c1.x), "f"(0.0f) : "memory");
        asm volatile("st.global.cg.v4.f32 [%0], {%1,%2,%3,%4};"
                     :: "l"(dst + 3), "f"(c1.y), "f"(c1.z), "f"(c1.w), "f"(0.0f) : "memory");
    }

    // ---- Planes + stage this block's 512 points while pad stores drain
    __shared__ float4 plane[4];
    __shared__ float  spts[1536];
    if (threadIdx.x < 4) {
        const float* yp = y_pred + (b * 4 + threadIdx.x) * 4;
        float nx = yp[0], ny = yp[1], nz = yp[2];
        float inv = rsqrtf(nx*nx + ny*ny + nz*nz);
        plane[threadIdx.x] = make_float4(nx*inv, ny*inv, nz*inv, yp[3]);
    }
    {
        const float4* src = (const float4*)(points + ((size_t)b * N_ + n0) * 3);
        ((float4*)spts)[threadIdx.x] = src[threadIdx.x];
        if (threadIdx.x < 128)
            ((float4*)spts)[threadIdx.x + 256] = src[threadIdx.x + 256];
    }
    __syncthreads();

    // ---- Compute all 8 gather offsets before waiting
    int off[8];
#pragma unroll
    for (int k = 0; k < 2; k++) {
        const int p = threadIdx.x + (k << 8);
        const float px = spts[3 * p + 0];
        const float py = spts[3 * p + 1];
        const float pz = spts[3 * p + 2];
#pragma unroll
        for (int c = 0; c < 4; c++) {
            float4 pl = plane[c];
            float t  = 2.0f * (px*pl.x + py*pl.y + pz*pl.z + pl.w);
            float rx = fmaf(-t, pl.x, px);
            float ry = fmaf(-t, pl.y, py);
            float rz = fmaf(-t, pl.z, pz);
            int v0 = min(RES_ - 1, max(0, __float2int_rd(rx * (float)RES_)));
            int v1 = min(RES_ - 1, max(0, __float2int_rd(ry * (float)RES_)));
            int v2 = min(RES_ - 1, max(0, __float2int_rd(rz * (float)RES_)));
            off[k * 4 + c] = (v0 << 10) | (v1 << 5) | v2;
        }
    }

    // ---- Publish my pad slice; relaxed spin until whole batch slice ready
    if (threadIdx.x == 0) {
        int seen;
        asm volatile("atom.release.gpu.global.add.s32 %0, [%1], 1;"
                     : "=r"(seen) : "l"(&g_batch_ready[b]) : "memory");
        if (seen + 1 < 32) {
            int r;
            do {
                __nanosleep(32);
                asm volatile("ld.relaxed.gpu.global.s32 %0, [%1];"
                             : "=r"(r) : "l"(&g_batch_ready[b]) : "memory");
            } while (r < 32);
        }
    }
    __syncthreads();

    // ---- Phase 3: gathers, single math pass, two accumulators
    const float4* cpb = g_cp_pad + (b << 15);
    float acc0 = 0.0f, acc1 = 0.0f;
#pragma unroll
    for (int k = 0; k < 2; k++) {
        float4 cv[4];
#pragma unroll
        for (int c = 0; c < 4; c++) {
            asm volatile("ld.global.cg.v4.f32 {%0,%1,%2,%3}, [%4];"
                         : "=f"(cv[c].x), "=f"(cv[c].y), "=f"(cv[c].z), "=f"(cv[c].w)
                         : "l"(cpb + off[k * 4 + c]));
        }
        const int p = threadIdx.x + (k << 8);
        const float px = spts[3 * p + 0];
        const float py = spts[3 * p + 1];
        const float pz = spts[3 * p + 2];
#pragma unroll
        for (int c = 0; c < 4; c++) {
            float4 pl = plane[c];
            float t  = 2.0f * (px*pl.x + py*pl.y + pz*pl.z + pl.w);
            float rx = fmaf(-t, pl.x, px);
            float ry = fmaf(-t, pl.y, py);
            float rz = fmaf(-t, pl.z, pz);
            float dx = rx - cv[c].x, dy = ry - cv[c].y, dz = rz - cv[c].z;
            float s  = sqrtf(fmaf(dx, dx, fmaf(dy, dy, dz * dz)));
            if (c & 1) acc1 += s; else acc0 += s;
        }
    }
    float acc = acc0 + acc1;

    // ---- Deterministic block reduction
#pragma unroll
    for (int o = 16; o >= 1; o >>= 1)
        acc += __shfl_xor_sync(0xffffffffu, acc, o);
    __shared__ float ws[8];
    const int wid = threadIdx.x >> 5;
    if ((threadIdx.x & 31) == 0) ws[wid] = acc;
    __syncthreads();

    __shared__ bool is_last;
    if (threadIdx.x == 0) {
        float s = 0.0f;
#pragma unroll
        for (int w = 0; w < 8; w++) s += ws[w];
        asm volatile("st.global.cg.f32 [%0], %1;"
                     :: "l"(&g_partials[blockIdx.x]), "f"(s) : "memory");
        int done;
        asm volatile("atom.release.gpu.global.add.s32 %0, [%1], 1;"
                     : "=r"(done) : "l"(&g_count) : "memory");
        is_last = (done == NB - 1);
    }
    __syncthreads();
    if (!is_last) return;

    // ---- Tail: last block only (single acquire fence total)
    asm volatile("fence.acq_rel.gpu;" ::: "memory");

    __shared__ float reg_s;
    if (threadIdx.x < 32) {
        const float* yp = y_pred + threadIdx.x * 16;
        float nh[4][3];
#pragma unroll
        for (int c = 0; c < 4; c++) {
            float nx = yp[c*4+0], ny = yp[c*4+1], nz = yp[c*4+2];
            float inv = rsqrtf(nx*nx + ny*ny + nz*nz);
            nh[c][0] = nx*inv; nh[c][1] = ny*inv; nh[c][2] = nz*inv;
        }
        float s = 0.0f;
#pragma unroll
        for (int c = 0; c < 4; c++)
#pragma unroll
            for (int e = 0; e < 4; e++) {
                float g = nh[c][0]*nh[e][0] + nh[c][1]*nh[e][1] + nh[c][2]*nh[e][2]
                          - (c == e ? 1.0f : 0.0f);
                s += g * g;
            }
        float reg = sqrtf(s);
#pragma unroll
        for (int o = 16; o >= 1; o >>= 1)
            reg += __shfl_xor_sync(0xffffffffu, reg, o);
        if (threadIdx.x == 0) reg_s = 25.0f * reg * (1.0f / (float)B_);
    }

    __shared__ float red[256];
    float a0, a1, a2, a3;
    {
        const float* p = g_partials;
        int i = threadIdx.x;
        asm volatile("ld.global.cg.f32 %0, [%1];" : "=f"(a0) : "l"(p + i));
        asm volatile("ld.global.cg.f32 %0, [%1];" : "=f"(a1) : "l"(p + i + 256));
        asm volatile("ld.global.cg.f32 %0, [%1];" : "=f"(a2) : "l"(p + i + 512));
        asm volatile("ld.global.cg.f32 %0, [%1];" : "=f"(a3) : "l"(p + i + 768));
    }
    red[threadIdx.x] = (a0 + a1) + (a2 + a3);
    __syncthreads();
#pragma unroll
    for (int stride = 128; stride >= 1; stride >>= 1) {
        if (threadIdx.x < stride) red[threadIdx.x] += red[threadIdx.x + stride];
        __syncthreads();
    }
    if (threadIdx.x == 0) {
        out[0] = red[0] * (1.0f / (float)N_) + reg_s;
#pragma unroll
        for (int i = 0; i < B_; i++) g_batch_ready[i] = 0;
        g_count = 0;
    }
}

extern "C" void kernel_launch(void* const* d_in, const int* in_sizes, int n_in,
                              void* d_out, int out_size) {
    const float* y_pred = (const float*)d_in[0];
    const float* points = (const float*)d_in[1];
    // d_in[2] = voxel_grid — unused by the reference math.
    const float4* cp4   = (const float4*)d_in[3];
    float* out = (float*)d_out;

    refl_kernel<<<NB, 256>>>(y_pred, points, cp4, out);
}